// round 17
// baseline (speedup 1.0000x reference)
#include <cuda_runtime.h>
#include <cuda_bf16.h>
#include <cstdint>

// ---------------- problem constants ----------------
#define NN      8192
#define DD      512
#define SS      64
#define TILE    128
#define NCHUNK  8                  // k-chunks per tile (64 bf16 elems each)
#define NSPLIT  2
#define NT      (NN / NSPLIT / TILE)   // 32 i-tiles per CTA
#define NTG     (NN / TILE)            // 64 global tiles
#define NCH_TOT (NT * NCHUNK)          // 256 A-chunks per CTA
#define ASTAGES 2
#define INV2SIG 0.0009765625f      // 1/(2*512)
#define LOG2E   1.4426950408889634f
#define CEXP    (INV2SIG * LOG2E)  // premultiplied exp2 constant

// ---------------- arch gating ----------------
#if defined(__CUDA_ARCH__)
#  if defined(__CUDA_ARCH_FEAT_SM103_ALL) || defined(__CUDA_ARCH_FEAT_SM100_ALL) || \
      defined(__CUDA_ARCH_FEAT_SM101_ALL) || \
      (defined(__CUDA_ARCH_SPECIFIC__)) || (defined(__CUDA_ARCH_FAMILY_SPECIFIC__))
#    define HAS_TCGEN05 1
#  else
#    define HAS_TCGEN05 0
#  endif
#else
#  define HAS_TCGEN05 0
#endif

// ---------------- smem layout (bytes) ----------------
#define SM_TMEMPTR   0
#define MB_AF(s)     (64  + (s) * 8)      // A stage full  [2]
#define MB_AE(s)     (80  + (s) * 8)      // A stage empty [2]
#define MB_BF        96                   // B resident full (1 commit)
#define MB_GF(b)     (104 + (b) * 8)      // G full [2]
#define MB_GC        120                  // G consumed (count=4)
#define MB_WF        128                  // W full (1 commit per tile)
#define MB_EB(b)     (136 + (b) * 8)      // MMA2 done, per tile-parity class [2]
#define SM_SQJ       512                  // 128 floats (premultiplied by CEXP)
#define SM_B         1024                 // resident B: 8 chunks x 16KB = 128KB
#define SM_A         (SM_B + 131072)      // 132096: 2 stages x 16KB
#define SM_K         (SM_A + ASTAGES * 16384)   // 164864: single 32KB (2 x 16KB k-chunks)
#define SM_W         (SM_K + 32768)       // 197632: single 32KB (hi 16KB + lo 16KB)
#define SM_TOTAL     (SM_W + 32768)       // 230400 (proven launchable)

// ---------------- TMEM layout (cols) ----------------
#define TM_D1A  0
#define TM_D1B  128
#define TM_D2   256
#define TM_COLS 512

#define SWZ(x) ((x) ^ (((x) >> 3) & 0x70))

// MMA1: kind::f16, dtype=F32(1), atype=btype=BF16(1), N=128, M=128
#define IDESC_MMA1 ((1u<<4) | (1u<<7) | (1u<<10) | ((128u/8u)<<17) | ((128u/16u)<<24))
// MMA2: kind::f16, dtype=F32(1), atype=btype=BF16(1), N=64,  M=128
#define IDESC_MMA2 ((1u<<4) | (1u<<7) | (1u<<10) | ((64u/8u)<<17)  | ((128u/16u)<<24))

// ---------------- scratch ----------------
__device__ float  g_sq[NN];
__device__ float  g_Epart[NSPLIT * NN * SS];              // [split][j][s]
__device__ double g_partial[128];
__device__ int    g_count = 0;
__device__ __align__(1024) char g_Xpk[NTG * NCHUNK * 16384];   // 8 MB bf16 swizzled X chunks
__device__ __align__(1024) char g_Wpk[NTG * 32768];            // 2 MB  swizzled W hi/lo images

// ---------------- helpers ----------------
static __device__ __forceinline__ uint32_t s2u(const void* p) {
    uint32_t a;
    asm("{ .reg .u64 t; cvta.to.shared.u64 t, %1; cvt.u32.u64 %0, t; }" : "=r"(a) : "l"(p));
    return a;
}

#if HAS_TCGEN05 || !defined(__CUDA_ARCH__)

// SW128 K-major SMEM descriptor: layout=2, version=1, SBO=64, LBO=1
static __device__ __forceinline__ uint64_t mkdesc(uint32_t addr) {
    return ((uint64_t)2 << 61) | ((uint64_t)1 << 46) | ((uint64_t)64 << 32) |
           ((uint64_t)1 << 16) | (uint64_t)((addr >> 4) & 0x3FFF);
}

static __device__ __forceinline__ void mbar_init(uint32_t a, uint32_t cnt) {
    asm volatile("mbarrier.init.shared.b64 [%0], %1;" :: "r"(a), "r"(cnt) : "memory");
}
static __device__ __forceinline__ void mbar_arrive(uint32_t a) {
    asm volatile("mbarrier.arrive.shared.b64 _, [%0];" :: "r"(a) : "memory");
}
static __device__ __forceinline__ void mbar_expect_tx(uint32_t a, uint32_t bytes) {
    asm volatile("mbarrier.arrive.expect_tx.shared.b64 _, [%0], %1;"
                 :: "r"(a), "r"(bytes) : "memory");
}
static __device__ __forceinline__ void mbar_wait(uint32_t a, uint32_t parity) {
    asm volatile(
        "{\n\t.reg .pred P;\n\t"
        "WL_%=:\n\t"
        "mbarrier.try_wait.parity.acquire.cta.shared::cta.b64 P, [%0], %1, 0x989680;\n\t"
        "@P bra.uni WD_%=;\n\t"
        "bra.uni WL_%=;\n\t"
        "WD_%=:\n\t}"
        :: "r"(a), "r"(parity) : "memory");
}
static __device__ __forceinline__ void bulk_cp(uint32_t dst, const void* src,
                                               uint32_t bytes, uint32_t mbar) {
    asm volatile(
        "cp.async.bulk.shared::cluster.global.mbarrier::complete_tx::bytes "
        "[%0], [%1], %2, [%3];"
        :: "r"(dst), "l"(src), "r"(bytes), "r"(mbar) : "memory");
}
static __device__ __forceinline__ void tc_commit(uint32_t mbar) {
    asm volatile(
        "tcgen05.commit.cta_group::1.mbarrier::arrive::one.shared::cluster.b64 [%0];"
        :: "r"(mbar) : "memory");
}
static __device__ __forceinline__ void mma_bf16(uint32_t d, uint64_t a, uint64_t b,
                                                uint32_t idesc, uint32_t en) {
    asm volatile(
        "{\n\t.reg .pred p;\n\tsetp.ne.u32 p, %4, 0;\n\t"
        "tcgen05.mma.cta_group::1.kind::f16 [%0], %1, %2, %3, {%5, %5, %5, %5}, p;\n\t}"
        :: "r"(d), "l"(a), "l"(b), "r"(idesc), "r"(en), "r"(0u) : "memory");
}

#define TC_LD_X32(r, addr) \
    asm volatile( \
        "tcgen05.ld.sync.aligned.32x32b.x32.b32 " \
        "{%0, %1, %2, %3, %4, %5, %6, %7, " \
        " %8, %9, %10, %11, %12, %13, %14, %15, " \
        " %16, %17, %18, %19, %20, %21, %22, %23, " \
        " %24, %25, %26, %27, %28, %29, %30, %31}, [%32];" \
        : "=r"((r)[0]),  "=r"((r)[1]),  "=r"((r)[2]),  "=r"((r)[3]), \
          "=r"((r)[4]),  "=r"((r)[5]),  "=r"((r)[6]),  "=r"((r)[7]), \
          "=r"((r)[8]),  "=r"((r)[9]),  "=r"((r)[10]), "=r"((r)[11]), \
          "=r"((r)[12]), "=r"((r)[13]), "=r"((r)[14]), "=r"((r)[15]), \
          "=r"((r)[16]), "=r"((r)[17]), "=r"((r)[18]), "=r"((r)[19]), \
          "=r"((r)[20]), "=r"((r)[21]), "=r"((r)[22]), "=r"((r)[23]), \
          "=r"((r)[24]), "=r"((r)[25]), "=r"((r)[26]), "=r"((r)[27]), \
          "=r"((r)[28]), "=r"((r)[29]), "=r"((r)[30]), "=r"((r)[31]) \
        : "r"(addr))

#define TC_WAIT_LD()      asm volatile("tcgen05.wait::ld.sync.aligned;" ::: "memory")
#define TC_FENCE_AFTER()  asm volatile("tcgen05.fence::after_thread_sync;" ::: "memory")
#define TC_FENCE_BEFORE() asm volatile("tcgen05.fence::before_thread_sync;" ::: "memory")
#define FENCE_ASYNC()     asm volatile("fence.proxy.async.shared::cta;" ::: "memory")

#endif // helpers

// ---------------------------------------------------------------------------
// Kernel 1: row squared norms (exact fp32 X)
// ---------------------------------------------------------------------------
__global__ void rownorm_kernel(const float* __restrict__ X) {
    int row  = blockIdx.x * 8 + (threadIdx.x >> 5);
    int lane = threadIdx.x & 31;
    const float4* xr = reinterpret_cast<const float4*>(X + (size_t)row * DD);
    float s = 0.f;
#pragma unroll
    for (int q = 0; q < 4; q++) {
        float4 v = xr[lane + q * 32];
        s += v.x * v.x + v.y * v.y + v.z * v.z + v.w * v.w;
    }
#pragma unroll
    for (int o = 16; o; o >>= 1) s += __shfl_xor_sync(0xFFFFFFFFu, s, o);
    if (lane == 0) g_sq[row] = s;
}

// ---------------------------------------------------------------------------
// Kernel 1b: pack X into bf16 swizzled 16KB chunk images
// ---------------------------------------------------------------------------
__global__ void xpack_kernel(const float* __restrict__ X) {
    const int gt = blockIdx.x, c = blockIdx.y;
    const int row = threadIdx.x;
    const float* src = &X[(size_t)(gt * TILE + row) * DD + c * 64];
    char* out = g_Xpk + ((size_t)gt * NCHUNK + c) * 16384;
#pragma unroll
    for (int u = 0; u < 8; u++) {
        float4 a = *reinterpret_cast<const float4*>(src + u * 8);
        float4 b = *reinterpret_cast<const float4*>(src + u * 8 + 4);
        __nv_bfloat162 p0 = __floats2bfloat162_rn(a.x, a.y);
        __nv_bfloat162 p1 = __floats2bfloat162_rn(a.z, a.w);
        __nv_bfloat162 p2 = __floats2bfloat162_rn(b.x, b.y);
        __nv_bfloat162 p3 = __floats2bfloat162_rn(b.z, b.w);
        uint4 v;
        v.x = *reinterpret_cast<uint32_t*>(&p0);
        v.y = *reinterpret_cast<uint32_t*>(&p1);
        v.z = *reinterpret_cast<uint32_t*>(&p2);
        v.w = *reinterpret_cast<uint32_t*>(&p3);
        *reinterpret_cast<uint4*>(out + SWZ(row * 128 + u * 16)) = v;
    }
}

// ---------------------------------------------------------------------------
// Kernel 1c: pack W into per-tile bf16 hi/lo swizzled 32KB images
// ---------------------------------------------------------------------------
__global__ void wpack_kernel(const float* __restrict__ W) {
    const int gt = blockIdx.x;
    const int t = threadIdx.x;
    char* out = g_Wpk + (size_t)gt * 32768;
#pragma unroll
    for (int m = 0; m < 32; m++) {
        int flat = m * 256 + t;
        int iw = flat >> 6, s = flat & 63;
        float v = W[(size_t)(gt * TILE + iw) * SS + s];
        __nv_bfloat16 h = __float2bfloat16_rn(v);
        __nv_bfloat16 l = __float2bfloat16_rn(v - __bfloat162float(h));
        int c2 = iw >> 6;
        int sw = SWZ(s * 128 + (iw & 63) * 2);
        *reinterpret_cast<__nv_bfloat16*>(out + c2 * 8192 + sw) = h;
        *reinterpret_cast<__nv_bfloat16*>(out + 16384 + c2 * 8192 + sw) = l;
    }
}

// ---------------------------------------------------------------------------
// Kernel 2: warp-specialized tcgen05 pipeline, B SMEM-resident.
// grid (64 j-tiles, 2 i-splits), 192 threads.
//   warp 0 lane 0 : MMA1 issuer
//   warp 5 lane 0 : copy issuer (B once, then A stream + W per tile)
//   warps 1-4     : consumer (frozen 4-warp topology)
// Wait rule (verified): m-th commit on a barrier -> parity (m+1)&1, with
// e <= m guaranteed by issue-order counting at every wait site.
// ---------------------------------------------------------------------------
__global__ __launch_bounds__(192, 1)
void kpca_mma_kernel() {
    extern __shared__ char smem[];
#if HAS_TCGEN05
    const uint32_t sb = s2u(smem);
    const int t    = threadIdx.x;
    const int wid  = t >> 5;
    const int lane = t & 31;
    const int jt     = blockIdx.x;
    const int isplit = blockIdx.y;
    const int j0     = jt * TILE;

    if (wid == 0) {
        asm volatile("tcgen05.alloc.cta_group::1.sync.aligned.shared::cta.b32 [%0], %1;"
                     :: "r"(sb + SM_TMEMPTR), "r"((uint32_t)TM_COLS) : "memory");
    }
    if (t == 0) {
#pragma unroll
        for (int s = 0; s < ASTAGES; s++) { mbar_init(sb + MB_AF(s), 1); mbar_init(sb + MB_AE(s), 1); }
        mbar_init(sb + MB_BF, 1);
        mbar_init(sb + MB_GF(0), 1);  mbar_init(sb + MB_GF(1), 1);
        mbar_init(sb + MB_GC, 4);
        mbar_init(sb + MB_WF, 1);
        mbar_init(sb + MB_EB(0), 1);  mbar_init(sb + MB_EB(1), 1);
    }
    if (t < 128) ((float*)(smem + SM_SQJ))[t] = g_sq[j0 + t] * CEXP;  // premultiplied
    __syncthreads();

    uint32_t tb;
    asm volatile("ld.shared.b32 %0, [%1];" : "=r"(tb) : "r"(sb + SM_TMEMPTR));

    if (wid == 0) {
        // ================= MMA1 ISSUER (warp 0 lane 0) =================
        if (lane == 0) {
            mbar_wait(sb + MB_BF, 0);   // B resident (m=1, P=0)
            for (int gm = 0; gm < NCH_TOT; gm++) {
                const int it = gm >> 3, c = gm & 7, s = gm & 1;
                if (c == 0 && it >= 2) mbar_wait(sb + MB_GC, it & 1);  // epi(it-2) LDTM done
                // A stage fill #(gm>>1)+1: P = (gm>>1)&1
                mbar_wait(sb + MB_AF(s), (gm >> 1) & 1);
                uint64_t ad = mkdesc(sb + SM_A + s * 16384);
                uint64_t bd = mkdesc(sb + SM_B + c * 16384);
                uint32_t d1 = tb + ((it & 1) ? TM_D1B : TM_D1A);
#pragma unroll
                for (int ss = 0; ss < 4; ss++)
                    mma_bf16(d1, ad + ss * 2, bd + ss * 2, IDESC_MMA1, (c | ss) != 0);
                tc_commit(sb + MB_AE(s));
                if (c == 7) tc_commit(sb + MB_GF(it & 1));
            }
        }
    } else if (wid == 5) {
        // ================= COPY ISSUER (warp 5 lane 0) =================
        if (lane == 0) {
            const char* xpkA = g_Xpk + (size_t)(isplit * NT) * NCHUNK * 16384;
            const char* xpkB = g_Xpk + (size_t)jt * NCHUNK * 16384;
            // B resident: one expect covering all 8 chunk copies
            mbar_expect_tx(sb + MB_BF, 131072);
#pragma unroll
            for (int c = 0; c < NCHUNK; c++)
                bulk_cp(sb + SM_B + c * 16384, xpkB + (size_t)c * 16384,
                        16384, sb + MB_BF);
            for (int g = 0; g < NCH_TOT; g++) {
                const int it_c = g >> 3, c_c = g & 7;
                if (c_c == 0) {
                    // W buffer free once MMA2(it_c-1) done:
                    // y=it_c-1 on barrier y&1, m=(y>>1)+1, P=(y>>1)&1
                    if (it_c >= 1) {
                        const int y = it_c - 1;
                        mbar_wait(sb + MB_EB(y & 1), (y >> 1) & 1);
                    }
                    mbar_expect_tx(sb + MB_WF, 32768);
                    bulk_cp(sb + SM_W,
                            g_Wpk + (size_t)(isplit * NT + it_c) * 32768,
                            32768, sb + MB_WF);
                }
                const int s = g & 1;
                // A stage reuse: commit #(g>>1) consumed: P = ((g>>1)+1)&1
                if (g >= ASTAGES) mbar_wait(sb + MB_AE(s), ((g >> 1) + 1) & 1);
                mbar_expect_tx(sb + MB_AF(s), 16384);
                bulk_cp(sb + SM_A + s * 16384,
                        xpkA + ((size_t)it_c * NCHUNK + c_c) * 16384,
                        16384, sb + MB_AF(s));
            }
        }
    } else {
        // ========== CONSUMER (warps 1-4, 128 threads) — frozen topology ==========
        const int sub  = wid & 3;               // TMEM subpartition
        const int iloc = sub * 32 + lane;       // i row owned by this thread
        const int ic   = iloc >> 6;             // k-chunk of MMA2
        const int ii2  = (iloc & 63) * 2;       // byte offset in K row
        const int KhiC = SM_K + ic * 16384;
        const float* sqs = (const float*)(smem + SM_SQJ);   // premultiplied by CEXP

        for (int ite = 0; ite < NT; ite++) {
            const uint32_t d1 = tb + ((ite & 1) ? TM_D1B : TM_D1A);
            const float base = -g_sq[isplit * (NN / NSPLIT) + ite * TILE + iloc] * CEXP;

            mbar_wait(sb + MB_GF(ite & 1), (ite >> 1) & 1);
            TC_FENCE_AFTER();
            // K buffer free once MMA2(ite-1) done: y=ite-1, barrier y&1, P=(y>>1)&1
            if (ite >= 1) {
                const int y = ite - 1;
                mbar_wait(sb + MB_EB(y & 1), (y >> 1) & 1);
            }

#pragma unroll
            for (int p = 0; p < 2; p++) {
                uint32_t r[64];
                TC_LD_X32(r,      d1 + p * 64);
                TC_LD_X32(r + 32, d1 + p * 64 + 32);
                TC_WAIT_LD();
                if (p == 1 && lane == 0) mbar_arrive(sb + MB_GC);  // D1 WAR release
#pragma unroll
                for (int rr = 0; rr < 64; rr++) {
                    int   j  = p * 64 + rr;
                    float gv = __uint_as_float(r[rr]);
                    float v  = exp2f(fmaf(gv, 2.0f * CEXP, base - sqs[j]));
                    *reinterpret_cast<__nv_bfloat16*>(smem + KhiC + SWZ(j * 128 + ii2)) =
                        __float2bfloat16_rn(v);
                }
            }
            FENCE_ASYNC();
            asm volatile("bar.sync 1, 128;" ::: "memory");

            if (t == 32) {   // warp 1 lane 0 issues MMA2
                // W(ite) ready: commit #(ite+1) on MB_WF: P = (ite+2)&1 = ite&1... P=(m+1)&1
                mbar_wait(sb + MB_WF, (ite + 1) & 1 ? 0 : 1);   // m=ite+1, P=(ite+2)&1
#pragma unroll
                for (int c2 = 0; c2 < 2; c2++) {
                    uint64_t ah = mkdesc(sb + SM_K + c2 * 16384);
                    uint64_t bh = mkdesc(sb + SM_W + c2 * 8192);
                    uint64_t bl = mkdesc(sb + SM_W + 16384 + c2 * 8192);
#pragma unroll
                    for (int ss = 0; ss < 4; ss++) {
                        uint32_t first = (ite == 0 && c2 == 0 && ss == 0);
                        mma_bf16(tb + TM_D2, ah + ss * 2, bh + ss * 2, IDESC_MMA2, !first);
                        mma_bf16(tb + TM_D2, ah + ss * 2, bl + ss * 2, IDESC_MMA2, 1u);
                    }
                }
                tc_commit(sb + MB_EB(ite & 1));
            }
        }

        // ---------------- final E readout ----------------
        // last MMA2 = tile NT-1 (barrier 1, commit #(NT/2)=16): P = 17&1 = 1
        mbar_wait(sb + MB_EB(1), ((NT >> 1) + 1) & 1);
        TC_FENCE_AFTER();
        {
            uint32_t e[64];
            TC_LD_X32(e,      tb + TM_D2);
            TC_LD_X32(e + 32, tb + TM_D2 + 32);
            TC_WAIT_LD();
            TC_FENCE_BEFORE();
            float* dst = &g_Epart[(size_t)isplit * NN * SS + (size_t)(j0 + iloc) * SS];
#pragma unroll
            for (int q = 0; q < 16; q++)
                reinterpret_cast<float4*>(dst)[q] =
                    make_float4(__uint_as_float(e[q * 4 + 0]), __uint_as_float(e[q * 4 + 1]),
                                __uint_as_float(e[q * 4 + 2]), __uint_as_float(e[q * 4 + 3]));
        }
    }

    __syncthreads();
    if (wid == 0) {
        asm volatile("tcgen05.relinquish_alloc_permit.cta_group::1.sync.aligned;" ::: "memory");
        asm volatile("tcgen05.dealloc.cta_group::1.sync.aligned.b32 %0, %1;"
                     :: "r"(tb), "r"((uint32_t)TM_COLS));
    }
#else
    (void)smem;
#endif
}

// ---------------------------------------------------------------------------
// Kernel 3: fused finalize (partials -> loss -> last-block final reduction)
// ---------------------------------------------------------------------------
__global__ void finalize_kernel(const float* __restrict__ W,
                                const float* __restrict__ invl,
                                float* __restrict__ out) {
    const int tid = threadIdx.x;
    const int b   = blockIdx.x;

    double contrib = 0.0;
#pragma unroll
    for (int q = 0; q < 4; q++) {
        int idx = b * 4096 + q * 1024 + tid;
        int j = idx >> 6;
        int s = idx & 63;
        float E = g_Epart[idx] + g_Epart[NN * SS + idx];
        double Ed = (double)E;
        contrib += 0.5 * Ed * ((double)W[(size_t)j * SS + s] - (double)invl[s] * Ed);
    }

    __shared__ double sm[1024];
    sm[tid] = contrib;
    __syncthreads();
#pragma unroll
    for (int o = 512; o; o >>= 1) {
        if (tid < o) sm[tid] += sm[tid + o];
        __syncthreads();
    }

    __shared__ int isLast;
    if (tid == 0) {
        g_partial[b] = sm[0];
        __threadfence();
        isLast = (atomicAdd(&g_count, 1) == 127);
    }
    __syncthreads();

    if (isLast) {
        double v = (tid < 128) ? g_partial[tid] : 0.0;
        sm[tid] = v;
        __syncthreads();
#pragma unroll
        for (int o = 64; o; o >>= 1) {
            if (tid < o) sm[tid] += sm[tid + o];
            __syncthreads();
        }
        if (tid == 0) {
            double L = sm[0];
            out[0] = (float)(L + 0.05 * L * L);
            g_count = 0;   // reset for next graph replay
        }
    }
}

// ---------------------------------------------------------------------------
extern "C" void kernel_launch(void* const* d_in, const int* in_sizes, int n_in,
                              void* d_out, int out_size) {
    const float* X    = (const float*)d_in[0];   // [8192, 512]
    const float* W    = (const float*)d_in[1];   // [8192, 64]
    const float* invl = (const float*)d_in[2];   // [64]
    float* out = (float*)d_out;

    cudaFuncSetAttribute(kpca_mma_kernel,
                         cudaFuncAttributeMaxDynamicSharedMemorySize, SM_TOTAL);

    rownorm_kernel<<<NN / 8, 256>>>(X);
    xpack_kernel<<<dim3(NTG, NCHUNK), 128>>>(X);
    wpack_kernel<<<NTG, 256>>>(W);
    kpca_mma_kernel<<<dim3(NTG, NSPLIT), 192, SM_TOTAL>>>();
    finalize_kernel<<<128, 1024>>>(W, invl, out);
}